// round 10
// baseline (speedup 1.0000x reference)
#include <cuda_runtime.h>
#include <cuda_fp16.h>
#include <mma.h>
#include <math.h>

using namespace nvcuda;

#define NN 100000
#define EE 1000000
#define SCH 512                     // scan chunk
#define NBLK ((NN + SCH - 1) / SCH) // 196
#define NB 64                       // degree buckets

// Scratch (device globals — no allocation allowed)
__device__ int   g_is32;
__device__ int   g_src[EE];
__device__ int   g_dst[EE];
__device__ int   g_csr[EE];
__device__ int   g_degi[NN];
__device__ int   g_off[NN + 1];
__device__ int   g_cur[NN];
__device__ int   g_part[NBLK];
__device__ int   g_carry[NBLK];
__device__ int   g_bhist[NB * NBLK];
__device__ int   g_bstart[NB * NBLK];
__device__ int   g_perm[NN];
__device__ float g_dinv[NN];
__device__ __align__(16) float  g_b1p[112];
__device__ __align__(16) float  g_b2p[64];
__device__ __align__(16) __half g_w1h[64 * 112];
__device__ __align__(16) __half g_w2h[112 * 64];
__device__ __align__(16) __half g_w3h[64 * 32];
__device__ __align__(16) __half g_hx[(size_t)NN * 64];
__device__ __align__(16) __half g_h1[(size_t)NN * 64];
__device__ __align__(16) __half g_h2[(size_t)NN * 112];

// ---------------- setup: zero deg + dtype detect + x->half ----------------
__global__ void k_setup(const float* __restrict__ x, __half* __restrict__ xh,
                        const long long* __restrict__ edge64, int E) {
    int idx = blockIdx.x * blockDim.x + threadIdx.x;
    if (idx < NN) g_degi[idx] = 0;
    if (idx < NN * 8) {
        float4 a = *(const float4*)(x + (size_t)idx * 8);
        float4 b = *(const float4*)(x + (size_t)idx * 8 + 4);
        __half2 h[4];
        h[0] = __float22half2_rn(make_float2(a.x, a.y));
        h[1] = __float22half2_rn(make_float2(a.z, a.w));
        h[2] = __float22half2_rn(make_float2(b.x, b.y));
        h[3] = __float22half2_rn(make_float2(b.z, b.w));
        *(uint4*)(xh + (size_t)idx * 8) = *(uint4*)h;
    }
    if (blockIdx.x == 0) {
        if (threadIdx.x == 0) g_is32 = 0;
        __syncthreads();
        int nscan = E < 4096 ? E : 4096;
        for (int j = threadIdx.x; j < nscan; j += blockDim.x) {
            long long v = edge64[j];
            if (v < 0 || v >= NN) g_is32 = 1;  // benign race
        }
    }
}

// convert + degree count in one edge pass
__global__ void k_convert_count(const void* __restrict__ edge, int E) {
    int e = blockIdx.x * blockDim.x + threadIdx.x;
    if (e >= E) return;
    int s, d;
    if (g_is32) {
        const int* p = (const int*)edge;
        s = p[e]; d = p[E + e];
    } else {
        const long long* p = (const long long*)edge;
        s = (int)p[e]; d = (int)p[E + e];
    }
    g_src[e] = s;
    g_dst[e] = d;
    atomicAdd(&g_degi[d], 1);
}

// ---------------- scan part: dinv + edge partials + degree histogram ----------------
__global__ void k_scan_part() {
    __shared__ int s[SCH];
    __shared__ int hist[NB];
    int t = threadIdx.x;
    if (t < NB) hist[t] = 0;
    __syncthreads();
    int i = blockIdx.x * SCH + t;
    int d = 0;
    if (i < NN) {
        d = g_degi[i];
        g_dinv[i] = rsqrtf((float)d + 1.0f);  // +1 self loop
        int bk = d < NB - 1 ? d : NB - 1;
        atomicAdd(&hist[bk], 1);
    }
    s[t] = d;
    __syncthreads();
    for (int o = SCH / 2; o > 0; o >>= 1) {
        if (t < o) s[t] += s[t + o];
        __syncthreads();
    }
    if (t == 0) g_part[blockIdx.x] = s[0];
    if (t < NB) g_bhist[t * NBLK + blockIdx.x] = hist[t];
}

__global__ void k_scan_top(int E) {
    __shared__ int s[256];
    int t = threadIdx.x;
    int v = (t < NBLK) ? g_part[t] : 0;
    s[t] = v;
    __syncthreads();
    for (int o = 1; o < 256; o <<= 1) {
        int u = (t >= o) ? s[t - o] : 0;
        __syncthreads();
        s[t] += u;
        __syncthreads();
    }
    if (t < NBLK) g_carry[t] = s[t] - v;  // exclusive
    if (t == 0) g_off[NN] = E;
}

__global__ void k_scan_fin() {
    __shared__ int s[SCH];
    int t = threadIdx.x;
    int i = blockIdx.x * SCH + t;
    int v = (i < NN) ? g_degi[i] : 0;
    s[t] = v;
    __syncthreads();
    for (int o = 1; o < SCH; o <<= 1) {
        int u = (t >= o) ? s[t - o] : 0;
        __syncthreads();
        s[t] += u;
        __syncthreads();
    }
    if (i < NN) {
        int off = g_carry[blockIdx.x] + s[t] - v;  // exclusive
        g_off[i] = off;
        g_cur[i] = off;
    }
}

__global__ void k_fill(int E) {
    int e = blockIdx.x * blockDim.x + threadIdx.x;
    if (e >= E) return;
    int pos = atomicAdd(&g_cur[g_dst[e]], 1);
    g_csr[pos] = g_src[e];
}

// ---------------- bucket scan (one block) + weight/bias pad+convert ----------------
__global__ void k_bscan_padw(const float* __restrict__ W1, const float* __restrict__ W2,
                             const float* __restrict__ W3, const float* __restrict__ b1,
                             const float* __restrict__ b2) {
    __shared__ int sums[256];
    const int n = NB * NBLK;
    const int chunk = (n + 255) / 256;
    int t = threadIdx.x;
    int s = 0;
    for (int j = 0; j < chunk; j++) {
        int idx = t * chunk + j;
        if (idx < n) s += g_bhist[idx];
    }
    sums[t] = s;
    __syncthreads();
    for (int o = 1; o < 256; o <<= 1) {
        int u = (t >= o) ? sums[t - o] : 0;
        __syncthreads();
        sums[t] += u;
        __syncthreads();
    }
    int run = (t > 0) ? sums[t - 1] : 0;
    for (int j = 0; j < chunk; j++) {
        int idx = t * chunk + j;
        if (idx < n) {
            int v = g_bhist[idx];
            g_bstart[idx] = run;
            run += v;
        }
    }
    // weights / biases (independent)
    for (int i = t; i < 64 * 112; i += 256) {
        int r = i / 112, c = i - r * 112;
        g_w1h[i] = __float2half(c < 100 ? W1[r * 100 + c] : 0.0f);
    }
    for (int i = t; i < 112 * 64; i += 256) {
        int r = i / 64, c = i - r * 64;
        g_w2h[i] = __float2half((r < 100 && c < 50) ? W2[r * 50 + c] : 0.0f);
    }
    for (int i = t; i < 64 * 32; i += 256) {
        int r = i / 32, c = i - r * 32;
        g_w3h[i] = __float2half((r < 50 && c < 25) ? W3[r * 25 + c] : 0.0f);
    }
    if (t < 112) g_b1p[t] = (t < 100) ? b1[t] : 0.0f;
    if (t < 64)  g_b2p[t] = (t < 50)  ? b2[t] : 0.0f;
}

// ---------------- scatter nodes into degree-sorted permutation ----------------
__global__ void k_scatter_perm() {
    __shared__ int loc[NB];
    int t = threadIdx.x;
    if (t < NB) loc[t] = 0;
    __syncthreads();
    int i = blockIdx.x * SCH + t;
    if (i < NN) {
        int d = g_degi[i];
        int bk = d < NB - 1 ? d : NB - 1;
        int r = atomicAdd(&loc[bk], 1);
        g_perm[g_bstart[bk * NBLK + blockIdx.x] + r] = i;
    }
}

__device__ __forceinline__ void fma_half8(float* acc, uint4 raw, float w) {
    const __half2* hp = (const __half2*)&raw;
#pragma unroll
    for (int j = 0; j < 4; j++) {
        float2 f = __half22float2(hp[j]);
        acc[2 * j]     = fmaf(f.x, w, acc[2 * j]);
        acc[2 * j + 1] = fmaf(f.y, w, acc[2 * j + 1]);
    }
}

// ---------------- gather aggregation (degree-sorted order) ----------------
// res[i] = xh[i]*dinv_i^2 + sum_{s in N(i)} xh[s]*dinv_s*dinv_i ; opt relu(+bias)
// Thread group of C handles node g_perm[g]; 8 features per thread.
template <int C, int LD, bool BR>
__global__ void k_aggh(const __half* __restrict__ xh, __half* __restrict__ outh,
                       const float* __restrict__ bias) {
    int idx = blockIdx.x * blockDim.x + threadIdx.x;
    if (idx >= NN * C) return;
    int g = idx / C;
    int c = idx - g * C;
    int i = g_perm[g];
    float di = g_dinv[i];
    float s2 = di * di;
    float acc[8];
    {
        uint4 raw = *(const uint4*)(xh + (size_t)i * LD + c * 8);
        const __half2* hp = (const __half2*)&raw;
#pragma unroll
        for (int j = 0; j < 4; j++) {
            float2 f = __half22float2(hp[j]);
            acc[2 * j]     = f.x * s2;
            acc[2 * j + 1] = f.y * s2;
        }
    }
    int b = g_off[i], e = g_off[i + 1];
    int t = b;
    for (; t + 2 <= e; t += 2) {
        int s0 = g_csr[t];
        int s1 = g_csr[t + 1];
        float w0 = g_dinv[s0] * di;
        float w1 = g_dinv[s1] * di;
        uint4 r0 = *(const uint4*)(xh + (size_t)s0 * LD + c * 8);
        uint4 r1 = *(const uint4*)(xh + (size_t)s1 * LD + c * 8);
        fma_half8(acc, r0, w0);
        fma_half8(acc, r1, w1);
    }
    if (t < e) {
        int s0 = g_csr[t];
        float w0 = g_dinv[s0] * di;
        uint4 r0 = *(const uint4*)(xh + (size_t)s0 * LD + c * 8);
        fma_half8(acc, r0, w0);
    }
    if (BR) {
#pragma unroll
        for (int j = 0; j < 8; j++)
            acc[j] = fmaxf(acc[j] + bias[c * 8 + j], 0.0f);
    }
    __half2 h[4];
#pragma unroll
    for (int j = 0; j < 4; j++)
        h[j] = __float22half2_rn(make_float2(acc[2 * j], acc[2 * j + 1]));
    *(uint4*)(outh + (size_t)i * LD + c * 8) = *(uint4*)h;
}

// ---------------- wmma GEMM: Yh = [relu](Xh @ Wh [+ b]) ----------------
template <int KP, int NP, bool BR>
__global__ void k_gemm_wmma(const __half* __restrict__ X, const __half* __restrict__ W,
                            const float* __restrict__ bias, __half* __restrict__ Yh, int n) {
    constexpr int NT = NP / 16, KT = KP / 16;
    constexpr int SM_AB = 64 * KP * 2 + KP * NP * 2;
    constexpr int SM_O  = 64 * NP * 4;
    constexpr int SM = SM_AB > SM_O ? SM_AB : SM_O;
    __shared__ __align__(32) char sm[SM];
    __half* Xs = (__half*)sm;                       // [64, KP]
    __half* Ws = (__half*)(sm + 64 * KP * 2);       // [KP, NP]
    float*  Os = (float*)sm;                        // reused after K loop: [64, NP]

    int tid = threadIdx.x;
    int wid = tid >> 5;
    int base = blockIdx.x * 64;

    for (int i = tid; i < KP * NP / 8; i += blockDim.x)
        ((uint4*)Ws)[i] = ((const uint4*)W)[i];
    constexpr int RW = KP / 8;  // uint4 per row
    for (int i = tid; i < 64 * RW; i += blockDim.x) {
        int r = i / RW, c = i - r * RW;
        uint4 v = {0, 0, 0, 0};
        if (base + r < n) v = ((const uint4*)(X + (size_t)(base + r) * KP))[c];
        ((uint4*)Xs)[i] = v;
    }
    __syncthreads();

    wmma::fragment<wmma::accumulator, 16, 16, 16, float> cf[NT];
#pragma unroll
    for (int nt = 0; nt < NT; nt++) wmma::fill_fragment(cf[nt], 0.0f);

#pragma unroll
    for (int kt = 0; kt < KT; kt++) {
        wmma::fragment<wmma::matrix_a, 16, 16, 16, __half, wmma::row_major> af;
        wmma::load_matrix_sync(af, Xs + wid * 16 * KP + kt * 16, KP);
#pragma unroll
        for (int nt = 0; nt < NT; nt++) {
            wmma::fragment<wmma::matrix_b, 16, 16, 16, __half, wmma::row_major> bf;
            wmma::load_matrix_sync(bf, Ws + kt * 16 * NP + nt * 16, NP);
            wmma::mma_sync(cf[nt], af, bf, cf[nt]);
        }
    }
    __syncthreads();  // done with Xs/Ws; alias as Os
#pragma unroll
    for (int nt = 0; nt < NT; nt++)
        wmma::store_matrix_sync(Os + wid * 16 * NP + nt * 16, cf[nt], NP, wmma::mem_row_major);
    __syncthreads();

    constexpr int CW = NP / 4;  // float4 groups per row
    for (int i = tid; i < 64 * CW; i += blockDim.x) {
        int r = i / CW, c = i - r * CW;
        if (base + r >= n) continue;
        float4 v = ((const float4*)(Os + r * NP))[c];
        if (BR) {
            float4 bb = *(const float4*)(bias + c * 4);
            v.x = fmaxf(v.x + bb.x, 0.0f); v.y = fmaxf(v.y + bb.y, 0.0f);
            v.z = fmaxf(v.z + bb.z, 0.0f); v.w = fmaxf(v.w + bb.w, 0.0f);
        }
        __half2 h01 = __float22half2_rn(make_float2(v.x, v.y));
        __half2 h23 = __float22half2_rn(make_float2(v.z, v.w));
        uint2 pk = {*(unsigned*)&h01, *(unsigned*)&h23};
        *(uint2*)(Yh + (size_t)(base + r) * NP + c * 4) = pk;
    }
}

// ---------------- fused agg3 + epilogue MLP: one thread per (sorted) node ----------------
__global__ void k_agg3_final(const __half* __restrict__ xh, const float* __restrict__ b3,
                             const float* __restrict__ Wl1, const float* __restrict__ bl1,
                             const float* __restrict__ Wl2, const float* __restrict__ bl2,
                             const float* __restrict__ Wl3, const float* __restrict__ bl3,
                             float* __restrict__ out, int n) {
    __shared__ float sW1[25 * 25], sW2[25 * 10], sW3[10];
    __shared__ float sb3[25], sb1[25], sb2[10], sb3l;
    for (int i = threadIdx.x; i < 25 * 25; i += blockDim.x) sW1[i] = Wl1[i];
    for (int i = threadIdx.x; i < 25 * 10; i += blockDim.x) sW2[i] = Wl2[i];
    if (threadIdx.x < 10) sW3[threadIdx.x] = Wl3[threadIdx.x];
    if (threadIdx.x < 25) { sb3[threadIdx.x] = b3[threadIdx.x]; sb1[threadIdx.x] = bl1[threadIdx.x]; }
    if (threadIdx.x < 10) sb2[threadIdx.x] = bl2[threadIdx.x];
    if (threadIdx.x == 0) sb3l = bl3[0];
    __syncthreads();

    int j = blockIdx.x * blockDim.x + threadIdx.x;
    if (j >= n) return;
    int i = g_perm[j];

    float di = g_dinv[i];
    float s2 = di * di;
    float acc[32];
    {
        const uint4* p = (const uint4*)(xh + (size_t)i * 32);
#pragma unroll
        for (int q = 0; q < 4; q++) {
            uint4 raw = p[q];
            const __half2* hp = (const __half2*)&raw;
#pragma unroll
            for (int jj = 0; jj < 4; jj++) {
                float2 f = __half22float2(hp[jj]);
                acc[q * 8 + 2 * jj]     = f.x * s2;
                acc[q * 8 + 2 * jj + 1] = f.y * s2;
            }
        }
    }
    int b = g_off[i], e = g_off[i + 1];
    for (int t = b; t < e; t++) {
        int s = g_csr[t];
        float w = g_dinv[s] * di;
        const uint4* p = (const uint4*)(xh + (size_t)s * 32);
        uint4 r0 = p[0], r1 = p[1], r2 = p[2], r3 = p[3];
        fma_half8(acc,      r0, w);
        fma_half8(acc + 8,  r1, w);
        fma_half8(acc + 16, r2, w);
        fma_half8(acc + 24, r3, w);
    }

    float v[25];
#pragma unroll
    for (int f = 0; f < 25; f++)
        v[f] = fmaxf(acc[f] + sb3[f], 0.0f);

    float h1[25];
#pragma unroll
    for (int c = 0; c < 25; c++) {
        float a = sb1[c];
#pragma unroll
        for (int k = 0; k < 25; k++) a = fmaf(v[k], sW1[k * 25 + c], a);
        h1[c] = fmaxf(a, 0.0f);
    }
    float h2[10];
#pragma unroll
    for (int c = 0; c < 10; c++) {
        float a = sb2[c];
#pragma unroll
        for (int k = 0; k < 25; k++) a = fmaf(h1[k], sW2[k * 10 + c], a);
        h2[c] = fmaxf(a, 0.0f);
    }
    float o = sb3l;
#pragma unroll
    for (int k = 0; k < 10; k++) o = fmaf(h2[k], sW3[k], o);
    out[i] = fmaxf(o, 0.0f);
}

// ---------------- launch ----------------
extern "C" void kernel_launch(void* const* d_in, const int* in_sizes, int n_in,
                              void* d_out, int out_size) {
    const float* x   = (const float*)d_in[0];
    const float* W1  = (const float*)d_in[1];
    const float* b1  = (const float*)d_in[2];
    const float* W2  = (const float*)d_in[3];
    const float* b2  = (const float*)d_in[4];
    const float* W3  = (const float*)d_in[5];
    const float* b3  = (const float*)d_in[6];
    const float* Wl1 = (const float*)d_in[7];
    const float* bl1 = (const float*)d_in[8];
    const float* Wl2 = (const float*)d_in[9];
    const float* bl2 = (const float*)d_in[10];
    const float* Wl3 = (const float*)d_in[11];
    const float* bl3 = (const float*)d_in[12];
    const void* edge = d_in[13];
    int E = in_sizes[13] / 2;

    float *b1p, *b2p;
    __half *HX, *H1, *H2, *W1H, *W2H, *W3H;
    cudaGetSymbolAddress((void**)&b1p, g_b1p);
    cudaGetSymbolAddress((void**)&b2p, g_b2p);
    cudaGetSymbolAddress((void**)&HX,  g_hx);
    cudaGetSymbolAddress((void**)&H1,  g_h1);
    cudaGetSymbolAddress((void**)&H2,  g_h2);
    cudaGetSymbolAddress((void**)&W1H, g_w1h);
    cudaGetSymbolAddress((void**)&W2H, g_w2h);
    cudaGetSymbolAddress((void**)&W3H, g_w3h);

    const int T = 256;
    int gN = (NN + T - 1) / T;
    int gE = (E + T - 1) / T;

    // setup (zero deg + detect + x->half) + CSR build + degree sort
    k_setup<<<(NN * 8 + T - 1) / T, T>>>(x, HX, (const long long*)edge, E);
    k_convert_count<<<gE, T>>>(edge, E);
    k_scan_part<<<NBLK, SCH>>>();
    k_scan_top<<<1, 256>>>(E);
    k_scan_fin<<<NBLK, SCH>>>();
    k_bscan_padw<<<1, 256>>>(W1, W2, W3, b1, b2);
    k_fill<<<gE, T>>>(E);
    k_scatter_perm<<<NBLK, SCH>>>();

    int gemmG = (NN + 63) / 64;

    // ----- Layer 1: agg (64, sorted) -> half; wmma 64->112 (+b1,relu) -----
    k_aggh<8, 64, false><<<NN * 8 / T, T>>>(HX, H1, nullptr);
    k_gemm_wmma<64, 112, true><<<gemmG, 128>>>(H1, W1H, b1p, H2, NN);

    // ----- Layer 2: wmma 112->64 raw; agg (64, sorted) +b2,relu -----
    k_gemm_wmma<112, 64, false><<<gemmG, 128>>>(H2, W2H, nullptr, HX, NN);
    k_aggh<8, 64, true><<<NN * 8 / T, T>>>(HX, H1, b2p);

    // ----- Layer 3: wmma 64->32 raw; fused agg (32, sorted) + MLP epilogue -----
    k_gemm_wmma<64, 32, false><<<gemmG, 128>>>(H1, W3H, nullptr, H2, NN);
    k_agg3_final<<<gN, T>>>(H2, b3, Wl1, bl1, Wl2, bl2, Wl3, bl3, (float*)d_out, NN);
}

// round 11
// speedup vs baseline: 1.1550x; 1.1550x over previous
#include <cuda_runtime.h>
#include <cuda_fp16.h>
#include <mma.h>
#include <math.h>

using namespace nvcuda;

#define NN 100000
#define EE 1000000

// Scratch (device globals — no allocation allowed)
__device__ int   g_is32;
__device__ int   g_ctr;
__device__ int   g_csr[EE];
__device__ int   g_degi[NN];
__device__ int   g_off[NN];
__device__ int   g_cur[NN];
__device__ float g_dinv[NN];
__device__ __align__(16) float  g_b1p[112];
__device__ __align__(16) float  g_b2p[64];
__device__ __align__(16) __half g_w1h[64 * 112];
__device__ __align__(16) __half g_w2h[112 * 64];
__device__ __align__(16) __half g_w3h[64 * 32];
__device__ __align__(16) __half g_hx[(size_t)NN * 64];
__device__ __align__(16) __half g_h1[(size_t)NN * 64];
__device__ __align__(16) __half g_h2[(size_t)NN * 112];

// ---------------- setup: zero deg/ctr + dtype detect + x->half ----------------
__global__ void k_setup(const float* __restrict__ x, __half* __restrict__ xh,
                        const long long* __restrict__ edge64, int E) {
    int idx = blockIdx.x * blockDim.x + threadIdx.x;
    if (idx < NN) g_degi[idx] = 0;
    if (idx < NN * 8) {
        float4 a = *(const float4*)(x + (size_t)idx * 8);
        float4 b = *(const float4*)(x + (size_t)idx * 8 + 4);
        __half2 h[4];
        h[0] = __float22half2_rn(make_float2(a.x, a.y));
        h[1] = __float22half2_rn(make_float2(a.z, a.w));
        h[2] = __float22half2_rn(make_float2(b.x, b.y));
        h[3] = __float22half2_rn(make_float2(b.z, b.w));
        *(uint4*)(xh + (size_t)idx * 8) = *(uint4*)h;
    }
    if (blockIdx.x == 0) {
        if (threadIdx.x == 0) { g_is32 = 0; g_ctr = 0; }
        __syncthreads();
        int nscan = E < 4096 ? E : 4096;
        for (int j = threadIdx.x; j < nscan; j += blockDim.x) {
            long long v = edge64[j];
            if (v < 0 || v >= NN) g_is32 = 1;  // benign race
        }
    }
}

// ---------------- degree count (reads dst straight from edge buffer) ----------------
__global__ void k_count(const void* __restrict__ edge, int E) {
    int e = blockIdx.x * blockDim.x + threadIdx.x;
    if (e >= E) return;
    int d = g_is32 ? ((const int*)edge)[E + e]
                   : (int)((const long long*)edge)[E + e];
    atomicAdd(&g_degi[d], 1);
}

// ---------------- segment allocation (unordered CSR) + dinv ----------------
__global__ void k_alloc() {
    int i = blockIdx.x * blockDim.x + threadIdx.x;
    if (i >= NN) return;
    int d = g_degi[i];
    g_dinv[i] = rsqrtf((float)d + 1.0f);  // +1 self loop
    int off = atomicAdd(&g_ctr, d);
    g_off[i] = off;
    g_cur[i] = off;
}

// ---------------- CSR fill (decodes edge buffer directly) ----------------
__global__ void k_fill(const void* __restrict__ edge, int E) {
    int e = blockIdx.x * blockDim.x + threadIdx.x;
    if (e >= E) return;
    int s, d;
    if (g_is32) {
        const int* p = (const int*)edge;
        s = p[e]; d = p[E + e];
    } else {
        const long long* p = (const long long*)edge;
        s = (int)p[e]; d = (int)p[E + e];
    }
    int pos = atomicAdd(&g_cur[d], 1);
    g_csr[pos] = s;
}

// ---------------- weight/bias pad+convert (once per launch) ----------------
__global__ void k_padw(const float* __restrict__ W1, const float* __restrict__ W2,
                       const float* __restrict__ W3, const float* __restrict__ b1,
                       const float* __restrict__ b2) {
    int i = blockIdx.x * blockDim.x + threadIdx.x;
    if (i < 64 * 112) {
        int r = i / 112, c = i - r * 112;
        g_w1h[i] = __float2half(c < 100 ? W1[r * 100 + c] : 0.0f);
    } else if (i < 64 * 112 + 112 * 64) {
        int j = i - 64 * 112;
        int r = j / 64, c = j - r * 64;
        g_w2h[j] = __float2half((r < 100 && c < 50) ? W2[r * 50 + c] : 0.0f);
    } else if (i < 64 * 112 + 112 * 64 + 64 * 32) {
        int j = i - 64 * 112 - 112 * 64;
        int r = j / 32, c = j - r * 32;
        g_w3h[j] = __float2half((r < 50 && c < 25) ? W3[r * 25 + c] : 0.0f);
    }
    if (i < 112) g_b1p[i] = (i < 100) ? b1[i] : 0.0f;
    if (i < 64)  g_b2p[i] = (i < 50)  ? b2[i] : 0.0f;
}

__device__ __forceinline__ void fma_half8(float* acc, uint4 raw, float w) {
    const __half2* hp = (const __half2*)&raw;
#pragma unroll
    for (int j = 0; j < 4; j++) {
        float2 f = __half22float2(hp[j]);
        acc[2 * j]     = fmaf(f.x, w, acc[2 * j]);
        acc[2 * j + 1] = fmaf(f.y, w, acc[2 * j + 1]);
    }
}

// ---------------- gather aggregation (half payload, fp32 accum, half out) ----------------
// res[i] = xh[i]*dinv_i^2 + sum_{s in N(i)} xh[s]*dinv_s*dinv_i ; opt relu(+bias)
// Thread = 8 features. Edge loop unrolled x2.
template <int C, int LD, bool BR>
__global__ void k_aggh(const __half* __restrict__ xh, __half* __restrict__ outh,
                       const float* __restrict__ bias) {
    int idx = blockIdx.x * blockDim.x + threadIdx.x;
    if (idx >= NN * C) return;
    int i = idx / C;
    int c = idx - i * C;
    float di = g_dinv[i];
    float s2 = di * di;
    float acc[8];
    {
        uint4 raw = *(const uint4*)(xh + (size_t)i * LD + c * 8);
        const __half2* hp = (const __half2*)&raw;
#pragma unroll
        for (int j = 0; j < 4; j++) {
            float2 f = __half22float2(hp[j]);
            acc[2 * j]     = f.x * s2;
            acc[2 * j + 1] = f.y * s2;
        }
    }
    int b = g_off[i];
    int e = b + g_degi[i];
    int t = b;
    for (; t + 2 <= e; t += 2) {
        int s0 = g_csr[t];
        int s1 = g_csr[t + 1];
        float w0 = g_dinv[s0] * di;
        float w1 = g_dinv[s1] * di;
        uint4 r0 = *(const uint4*)(xh + (size_t)s0 * LD + c * 8);
        uint4 r1 = *(const uint4*)(xh + (size_t)s1 * LD + c * 8);
        fma_half8(acc, r0, w0);
        fma_half8(acc, r1, w1);
    }
    if (t < e) {
        int s0 = g_csr[t];
        float w0 = g_dinv[s0] * di;
        uint4 r0 = *(const uint4*)(xh + (size_t)s0 * LD + c * 8);
        fma_half8(acc, r0, w0);
    }
    if (BR) {
#pragma unroll
        for (int j = 0; j < 8; j++)
            acc[j] = fmaxf(acc[j] + bias[c * 8 + j], 0.0f);
    }
    __half2 h[4];
#pragma unroll
    for (int j = 0; j < 4; j++)
        h[j] = __float22half2_rn(make_float2(acc[2 * j], acc[2 * j + 1]));
    *(uint4*)(outh + (size_t)i * LD + c * 8) = *(uint4*)h;
}

// ---------------- wmma GEMM: Yh = [relu](Xh @ Wh [+ b]) ----------------
template <int KP, int NP, bool BR>
__global__ void k_gemm_wmma(const __half* __restrict__ X, const __half* __restrict__ W,
                            const float* __restrict__ bias, __half* __restrict__ Yh, int n) {
    constexpr int NT = NP / 16, KT = KP / 16;
    constexpr int SM_AB = 64 * KP * 2 + KP * NP * 2;
    constexpr int SM_O  = 64 * NP * 4;
    constexpr int SM = SM_AB > SM_O ? SM_AB : SM_O;
    __shared__ __align__(32) char sm[SM];
    __half* Xs = (__half*)sm;                       // [64, KP]
    __half* Ws = (__half*)(sm + 64 * KP * 2);       // [KP, NP]
    float*  Os = (float*)sm;                        // reused after K loop: [64, NP]

    int tid = threadIdx.x;
    int wid = tid >> 5;
    int base = blockIdx.x * 64;

    for (int i = tid; i < KP * NP / 8; i += blockDim.x)
        ((uint4*)Ws)[i] = ((const uint4*)W)[i];
    constexpr int RW = KP / 8;  // uint4 per row
    for (int i = tid; i < 64 * RW; i += blockDim.x) {
        int r = i / RW, c = i - r * RW;
        uint4 v = {0, 0, 0, 0};
        if (base + r < n) v = ((const uint4*)(X + (size_t)(base + r) * KP))[c];
        ((uint4*)Xs)[i] = v;
    }
    __syncthreads();

    wmma::fragment<wmma::accumulator, 16, 16, 16, float> cf[NT];
#pragma unroll
    for (int nt = 0; nt < NT; nt++) wmma::fill_fragment(cf[nt], 0.0f);

#pragma unroll
    for (int kt = 0; kt < KT; kt++) {
        wmma::fragment<wmma::matrix_a, 16, 16, 16, __half, wmma::row_major> af;
        wmma::load_matrix_sync(af, Xs + wid * 16 * KP + kt * 16, KP);
#pragma unroll
        for (int nt = 0; nt < NT; nt++) {
            wmma::fragment<wmma::matrix_b, 16, 16, 16, __half, wmma::row_major> bf;
            wmma::load_matrix_sync(bf, Ws + kt * 16 * NP + nt * 16, NP);
            wmma::mma_sync(cf[nt], af, bf, cf[nt]);
        }
    }
    __syncthreads();  // done with Xs/Ws; alias as Os
#pragma unroll
    for (int nt = 0; nt < NT; nt++)
        wmma::store_matrix_sync(Os + wid * 16 * NP + nt * 16, cf[nt], NP, wmma::mem_row_major);
    __syncthreads();

    constexpr int CW = NP / 4;  // float4 groups per row
    for (int i = tid; i < 64 * CW; i += blockDim.x) {
        int r = i / CW, c = i - r * CW;
        if (base + r >= n) continue;
        float4 v = ((const float4*)(Os + r * NP))[c];
        if (BR) {
            float4 bb = *(const float4*)(bias + c * 4);
            v.x = fmaxf(v.x + bb.x, 0.0f); v.y = fmaxf(v.y + bb.y, 0.0f);
            v.z = fmaxf(v.z + bb.z, 0.0f); v.w = fmaxf(v.w + bb.w, 0.0f);
        }
        __half2 h01 = __float22half2_rn(make_float2(v.x, v.y));
        __half2 h23 = __float22half2_rn(make_float2(v.z, v.w));
        uint2 pk = {*(unsigned*)&h01, *(unsigned*)&h23};
        *(uint2*)(Yh + (size_t)(base + r) * NP + c * 4) = pk;
    }
}

// ---------------- fused agg3 + epilogue MLP: one thread per node ----------------
__global__ void k_agg3_final(const __half* __restrict__ xh, const float* __restrict__ b3,
                             const float* __restrict__ Wl1, const float* __restrict__ bl1,
                             const float* __restrict__ Wl2, const float* __restrict__ bl2,
                             const float* __restrict__ Wl3, const float* __restrict__ bl3,
                             float* __restrict__ out, int n) {
    __shared__ float sW1[25 * 25], sW2[25 * 10], sW3[10];
    __shared__ float sb3[25], sb1[25], sb2[10], sb3l;
    for (int i = threadIdx.x; i < 25 * 25; i += blockDim.x) sW1[i] = Wl1[i];
    for (int i = threadIdx.x; i < 25 * 10; i += blockDim.x) sW2[i] = Wl2[i];
    if (threadIdx.x < 10) sW3[threadIdx.x] = Wl3[threadIdx.x];
    if (threadIdx.x < 25) { sb3[threadIdx.x] = b3[threadIdx.x]; sb1[threadIdx.x] = bl1[threadIdx.x]; }
    if (threadIdx.x < 10) sb2[threadIdx.x] = bl2[threadIdx.x];
    if (threadIdx.x == 0) sb3l = bl3[0];
    __syncthreads();

    int i = blockIdx.x * blockDim.x + threadIdx.x;
    if (i >= n) return;

    float di = g_dinv[i];
    float s2 = di * di;
    float acc[32];
    {
        const uint4* p = (const uint4*)(xh + (size_t)i * 32);
#pragma unroll
        for (int q = 0; q < 4; q++) {
            uint4 raw = p[q];
            const __half2* hp = (const __half2*)&raw;
#pragma unroll
            for (int j = 0; j < 4; j++) {
                float2 f = __half22float2(hp[j]);
                acc[q * 8 + 2 * j]     = f.x * s2;
                acc[q * 8 + 2 * j + 1] = f.y * s2;
            }
        }
    }
    int b = g_off[i];
    int e = b + g_degi[i];
    for (int t = b; t < e; t++) {
        int s = g_csr[t];
        float w = g_dinv[s] * di;
        const uint4* p = (const uint4*)(xh + (size_t)s * 32);
        uint4 r0 = p[0], r1 = p[1], r2 = p[2], r3 = p[3];
        fma_half8(acc,      r0, w);
        fma_half8(acc + 8,  r1, w);
        fma_half8(acc + 16, r2, w);
        fma_half8(acc + 24, r3, w);
    }

    float v[25];
#pragma unroll
    for (int f = 0; f < 25; f++)
        v[f] = fmaxf(acc[f] + sb3[f], 0.0f);

    float h1[25];
#pragma unroll
    for (int c = 0; c < 25; c++) {
        float a = sb1[c];
#pragma unroll
        for (int k = 0; k < 25; k++) a = fmaf(v[k], sW1[k * 25 + c], a);
        h1[c] = fmaxf(a, 0.0f);
    }
    float h2[10];
#pragma unroll
    for (int c = 0; c < 10; c++) {
        float a = sb2[c];
#pragma unroll
        for (int k = 0; k < 25; k++) a = fmaf(h1[k], sW2[k * 10 + c], a);
        h2[c] = fmaxf(a, 0.0f);
    }
    float o = sb3l;
#pragma unroll
    for (int k = 0; k < 10; k++) o = fmaf(h2[k], sW3[k], o);
    out[i] = fmaxf(o, 0.0f);
}

// ---------------- launch ----------------
extern "C" void kernel_launch(void* const* d_in, const int* in_sizes, int n_in,
                              void* d_out, int out_size) {
    const float* x   = (const float*)d_in[0];
    const float* W1  = (const float*)d_in[1];
    const float* b1  = (const float*)d_in[2];
    const float* W2  = (const float*)d_in[3];
    const float* b2  = (const float*)d_in[4];
    const float* W3  = (const float*)d_in[5];
    const float* b3  = (const float*)d_in[6];
    const float* Wl1 = (const float*)d_in[7];
    const float* bl1 = (const float*)d_in[8];
    const float* Wl2 = (const float*)d_in[9];
    const float* bl2 = (const float*)d_in[10];
    const float* Wl3 = (const float*)d_in[11];
    const float* bl3 = (const float*)d_in[12];
    const void* edge = d_in[13];
    int E = in_sizes[13] / 2;

    float *b1p, *b2p;
    __half *HX, *H1, *H2, *W1H, *W2H, *W3H;
    cudaGetSymbolAddress((void**)&b1p, g_b1p);
    cudaGetSymbolAddress((void**)&b2p, g_b2p);
    cudaGetSymbolAddress((void**)&HX,  g_hx);
    cudaGetSymbolAddress((void**)&H1,  g_h1);
    cudaGetSymbolAddress((void**)&H2,  g_h2);
    cudaGetSymbolAddress((void**)&W1H, g_w1h);
    cudaGetSymbolAddress((void**)&W2H, g_w2h);
    cudaGetSymbolAddress((void**)&W3H, g_w3h);

    const int T = 256;
    int gN = (NN + T - 1) / T;
    int gE = (E + T - 1) / T;

    // setup (zero + detect + x->half) + unordered-CSR build
    k_setup<<<(NN * 8 + T - 1) / T, T>>>(x, HX, (const long long*)edge, E);
    k_count<<<gE, T>>>(edge, E);
    k_alloc<<<gN, T>>>();
    k_fill<<<gE, T>>>(edge, E);
    k_padw<<<64, T>>>(W1, W2, W3, b1, b2);

    int gemmG = (NN + 63) / 64;

    // ----- Layer 1: agg (64) -> half; wmma 64->112 (+b1,relu) -----
    k_aggh<8, 64, false><<<NN * 8 / T, T>>>(HX, H1, nullptr);
    k_gemm_wmma<64, 112, true><<<gemmG, 128>>>(H1, W1H, b1p, H2, NN);

    // ----- Layer 2: wmma 112->64 raw; agg (64) +b2,relu -----
    k_gemm_wmma<112, 64, false><<<gemmG, 128>>>(H2, W2H, nullptr, HX, NN);
    k_aggh<8, 64, true><<<NN * 8 / T, T>>>(HX, H1, b2p);

    // ----- Layer 3: wmma 64->32 raw; fused agg (32) + MLP epilogue -----
    k_gemm_wmma<64, 32, false><<<gemmG, 128>>>(H1, W3H, nullptr, H2, NN);
    k_agg3_final<<<gN, T>>>(H2, b3, Wl1, bl1, Wl2, bl2, Wl3, bl3, (float*)d_out, NN);
}